// round 4
// baseline (speedup 1.0000x reference)
#include <cuda_runtime.h>
#include <cstdint>

// YOLO loss, fused single kernel: cp.async double-buffered streaming +
// warp-ballot compaction of (rare) obj cells so the expensive double-softmax
// runs on ~1 warp per tile instead of all 4.

#define TILE      128
#define THREADS   128
#define NPART_MAX 2048
#define NV4       ((TILE * 30) / 4)      // 960 float4 per array per tile

__device__ float        g_part[6][NPART_MAX];
__device__ unsigned int g_count = 0;

__device__ __forceinline__ void cp_async16(void* smem_dst, const void* gmem_src)
{
    uint32_t s = (uint32_t)__cvta_generic_to_shared(smem_dst);
    asm volatile("cp.async.cg.shared.global [%0], [%1], 16;" :: "r"(s), "l"(gmem_src));
}
__device__ __forceinline__ void cp_commit() { asm volatile("cp.async.commit_group;" ::: "memory"); }
__device__ __forceinline__ void cp_wait1()  { asm volatile("cp.async.wait_group 1;" ::: "memory"); }
__device__ __forceinline__ void cp_wait0()  { asm volatile("cp.async.wait_group 0;" ::: "memory"); }

struct Stage {
    float sp[TILE * 30];
    float st[TILE * 30];
    int   sc[TILE];
};

__device__ __forceinline__ void prefetch_tile(Stage* stg,
                                              const float* __restrict__ pred,
                                              const float* __restrict__ target,
                                              const int*   __restrict__ choice,
                                              long long base_cell, int tid)
{
    const float4* pg = (const float4*)(pred   + base_cell * 30);
    const float4* tg = (const float4*)(target + base_cell * 30);
    float4* sp4 = (float4*)stg->sp;
    float4* st4 = (float4*)stg->st;
    #pragma unroll
    for (int i = tid; i < NV4; i += THREADS) cp_async16(&sp4[i], &pg[i]);
    #pragma unroll
    for (int i = tid; i < NV4; i += THREADS) cp_async16(&st4[i], &tg[i]);
    if (tid < TILE / 4) {
        const float4* cg = (const float4*)(choice + base_cell);
        cp_async16(&((float4*)stg->sc)[tid], &cg[tid]);
    }
}

// full obj-cell computation: loc, obj, cls terms into acc
__device__ __forceinline__ void obj_compute(const float* __restrict__ p,
                                            const float* __restrict__ t,
                                            bool c, float tconf, float acc[6])
{
    const int o = c ? 0 : 5;
    acc[4] += 1.f;
    float dx = p[o + 0] - t[o + 0];
    float dy = p[o + 1] - t[o + 1];
    float dw = p[o + 2] - sqrtf(t[o + 2]);
    float dh = p[o + 3] - sqrtf(t[o + 3]);
    acc[0] += 0.5f * (dx * dx + dy * dy) + 0.5f * (dw * dw + dh * dh);
    float tobj = c ? tconf : t[9];
    float d = p[o + 4] - tobj;
    acc[2] += d * d;
    // class CE: ce = log(sum(exp(sm))) - sm[argmax(tcls)], sm = softmax(logits)
    // (sm in [0,1] so the un-shifted LSE is numerically safe)
    float mx = -1e30f;
    #pragma unroll
    for (int k = 0; k < 20; k++) mx = fmaxf(mx, p[10 + k]);
    float sm[20];
    float den = 0.f;
    #pragma unroll
    for (int k = 0; k < 20; k++) { sm[k] = __expf(p[10 + k] - mx); den += sm[k]; }
    float inv = __fdividef(1.f, den);
    float den2 = 0.f;
    #pragma unroll
    for (int k = 0; k < 20; k++) { sm[k] *= inv; den2 += __expf(sm[k]); }
    float lse2 = __logf(den2);
    float bm = t[10]; int bi = 0;
    #pragma unroll
    for (int k = 1; k < 20; k++) { float v = t[10 + k]; if (v > bm) { bm = v; bi = k; } }
    acc[1] += lse2 - sm[bi];
}

__device__ __forceinline__ void block_reduce6(float* vals, float* s_red, int tid)
{
    #pragma unroll
    for (int v = 0; v < 6; v++) {
        #pragma unroll
        for (int off = 16; off > 0; off >>= 1)
            vals[v] += __shfl_down_sync(0xffffffffu, vals[v], off);
    }
    const int warp = tid >> 5;
    const int lane = tid & 31;
    if (lane == 0) {
        #pragma unroll
        for (int v = 0; v < 6; v++) s_red[warp * 6 + v] = vals[v];
    }
    __syncthreads();
    if (tid == 0) {
        #pragma unroll
        for (int v = 0; v < 6; v++)
            vals[v] = s_red[v] + s_red[6 + v] + s_red[12 + v] + s_red[18 + v];
    }
}

__global__ __launch_bounds__(THREADS)
void yolo_fused(const float* __restrict__ pred,
                const float* __restrict__ target,
                const int*   __restrict__ choice,
                float*       __restrict__ out,
                int n_cells, int n_tiles)
{
    __shared__ Stage stage[2];
    __shared__ float s_red[4 * 6];
    __shared__ bool  s_last;
    __shared__ int   s_list[TILE];
    __shared__ int   s_cnt;

    const int tid = threadIdx.x;
    float acc[6] = {0.f, 0.f, 0.f, 0.f, 0.f, 0.f};

    const int first = blockIdx.x;
    const int step  = gridDim.x;

    if (tid == 0) s_cnt = 0;

    int cur = 0;
    if (first < n_tiles) {
        long long base = (long long)first * TILE;
        if (base + TILE <= n_cells)
            prefetch_tile(&stage[0], pred, target, choice, base, tid);
        cp_commit();
    }

    for (int tile = first; tile < n_tiles; tile += step) {
        const long long base_cell = (long long)tile * TILE;
        const int cells_here = (int)min((long long)TILE, (long long)n_cells - base_cell);
        const bool full = (cells_here == TILE);

        const int next = tile + step;
        if (next < n_tiles) {
            long long nbase = (long long)next * TILE;
            if (nbase + TILE <= n_cells)
                prefetch_tile(&stage[cur ^ 1], pred, target, choice, nbase, tid);
            cp_commit();
            cp_wait1();
        } else {
            cp_wait0();
        }
        __syncthreads();   // stage ready; prior compute on this buffer done; s_cnt reset visible

        Stage* S = &stage[cur];

        if (full) {
            // ---- phase A: noobj terms (cheap, all lanes) + compact obj cells ----
            const float tconf = S->st[tid * 30 + 4];
            const bool  ob    = tconf > 0.f;
            if (!ob) {
                acc[5] += 1.f;
                float d0 = S->sp[tid * 30 + 4] - tconf;
                float d1 = S->sp[tid * 30 + 9] - S->st[tid * 30 + 9];
                acc[3] += d0 * d0 + d1 * d1;
            }
            unsigned int mask = __ballot_sync(0xffffffffu, ob);
            int base = 0;
            if ((tid & 31) == 0 && mask) base = atomicAdd(&s_cnt, __popc(mask));
            base = __shfl_sync(0xffffffffu, base, 0);
            if (ob) {
                int pos = base + __popc(mask & ((1u << (tid & 31)) - 1u));
                s_list[pos] = tid;
            }
            __syncthreads();   // list complete

            // ---- phase B: expensive obj path on ~s_cnt lanes only ----
            const int n_obj_tile = s_cnt;
            if (tid < n_obj_tile) {
                int cell = s_list[tid];
                const float* p = S->sp + cell * 30;
                const float* t = S->st + cell * 30;
                obj_compute(p, t, S->sc[cell] != 0, t[4], acc);
            }
        } else if (tid < cells_here) {
            // rare partial tail: straight from global
            const float* p = pred   + (base_cell + tid) * 30;
            const float* t = target + (base_cell + tid) * 30;
            float tconf = t[4];
            if (tconf > 0.f) {
                obj_compute(p, t, choice[base_cell + tid] != 0, tconf, acc);
            } else {
                acc[5] += 1.f;
                float d0 = p[4] - tconf;
                float d1 = p[9] - t[9];
                acc[3] += d0 * d0 + d1 * d1;
            }
        }

        __syncthreads();   // phase B done: safe to overwrite stage / reset s_cnt
        if (tid == 0) s_cnt = 0;
        cur ^= 1;
    }

    block_reduce6(acc, s_red, tid);

    if (tid == 0) {
        #pragma unroll
        for (int v = 0; v < 6; v++) g_part[v][blockIdx.x] = acc[v];
        __threadfence();
        unsigned int ticket = atomicAdd(&g_count, 1u);
        s_last = (ticket == gridDim.x - 1);
    }
    __syncthreads();

    if (s_last) {
        __threadfence();
        const int npart = gridDim.x;
        float a[6] = {0.f, 0.f, 0.f, 0.f, 0.f, 0.f};
        for (int i = tid; i < npart; i += THREADS) {
            #pragma unroll
            for (int v = 0; v < 6; v++) a[v] += g_part[v][i];
        }
        __syncthreads();
        block_reduce6(a, s_red, tid);
        if (tid == 0) {
            float n_obj = fmaxf(a[4], 1.f);
            float n_no  = fmaxf(a[5], 1.f);
            out[0] = 5.0f * a[0];
            out[1] = a[1] / n_obj;
            out[2] = a[2];
            out[3] = 0.5f * a[3] / n_no;
            g_count = 0;   // reset for next graph replay
        }
    }
}

extern "C" void kernel_launch(void* const* d_in, const int* in_sizes, int n_in,
                              void* d_out, int out_size)
{
    const float* pred   = (const float*)d_in[0];
    const float* target = (const float*)d_in[1];
    const int*   choice = (const int*)d_in[2];
    float* out = (float*)d_out;

    const int n_cells = in_sizes[2];
    const int n_tiles = (n_cells + TILE - 1) / TILE;

    int grid = 3 * 148;                       // 3 CTAs/SM (62.5 KB smem each)
    if (grid > n_tiles) grid = n_tiles;
    if (grid > NPART_MAX) grid = NPART_MAX;

    yolo_fused<<<grid, THREADS>>>(pred, target, choice, out, n_cells, n_tiles);
}

// round 5
// speedup vs baseline: 1.0525x; 1.0525x over previous
#include <cuda_runtime.h>
#include <cstdint>

// YOLO loss, fused single kernel: TMA (cp.async.bulk) double-buffered streaming.
// pred/target [N_CELLS, 30] f32, choice [N_CELLS] i32 -> 4 f32 scalars.
// One thread issues 3 bulk copies per tile into an mbarrier; all warps compute.

#define TILE      128
#define THREADS   128
#define NPART_MAX 2048
#define STAGE_PT_BYTES (TILE * 30 * 4)                       // 15360
#define STAGE_C_BYTES  (TILE * 4)                            // 512
#define STAGE_TX       (2 * STAGE_PT_BYTES + STAGE_C_BYTES)  // 31232

__device__ float        g_part[6][NPART_MAX];
__device__ unsigned int g_count = 0;

struct __align__(16) Stage {
    float sp[TILE * 30];   // offset 0
    float st[TILE * 30];   // offset 15360 (16B aligned)
    int   sc[TILE];        // offset 30720 (16B aligned)
};

__device__ __forceinline__ uint32_t smem_u32(const void* p)
{
    return (uint32_t)__cvta_generic_to_shared(p);
}
__device__ __forceinline__ void mbar_init(uint32_t mbar, uint32_t count)
{
    asm volatile("mbarrier.init.shared.b64 [%0], %1;" :: "r"(mbar), "r"(count) : "memory");
}
__device__ __forceinline__ void mbar_expect_tx(uint32_t mbar, uint32_t bytes)
{
    asm volatile("mbarrier.arrive.expect_tx.shared.b64 _, [%0], %1;"
                 :: "r"(mbar), "r"(bytes) : "memory");
}
__device__ __forceinline__ void bulk_g2s(uint32_t smem_dst, const void* gmem_src,
                                         uint32_t bytes, uint32_t mbar)
{
    asm volatile("cp.async.bulk.shared::cta.global.mbarrier::complete_tx::bytes "
                 "[%0], [%1], %2, [%3];"
                 :: "r"(smem_dst), "l"(gmem_src), "r"(bytes), "r"(mbar) : "memory");
}
__device__ __forceinline__ void fence_proxy_async_shared()
{
    asm volatile("fence.proxy.async.shared::cta;" ::: "memory");
}
__device__ __forceinline__ void mbar_wait(uint32_t mbar, uint32_t parity)
{
    asm volatile(
        "{\n\t"
        ".reg .pred P;\n\t"
        "WAIT_%=:\n\t"
        "mbarrier.try_wait.parity.acquire.cta.shared::cta.b64 P, [%0], %1, 0x989680;\n\t"
        "@P bra DONE_%=;\n\t"
        "bra WAIT_%=;\n\t"
        "DONE_%=:\n\t"
        "}"
        :: "r"(mbar), "r"(parity) : "memory");
}

// per-cell loss; acc[6] = {loc, cls, obj, noobj, m, nm}
__device__ __forceinline__ void cell_compute(const float* __restrict__ p,
                                             const float* __restrict__ t,
                                             bool c, float acc[6])
{
    const int o = c ? 0 : 5;
    const float tconf = t[4];

    if (tconf > 0.f) {
        acc[4] += 1.f;
        float dx = p[o + 0] - t[o + 0];
        float dy = p[o + 1] - t[o + 1];
        float dw = p[o + 2] - sqrtf(t[o + 2]);
        float dh = p[o + 3] - sqrtf(t[o + 3]);
        acc[0] += 0.5f * (dx * dx + dy * dy) + 0.5f * (dw * dw + dh * dh);
        float tobj = c ? tconf : t[9];
        float d = p[o + 4] - tobj;
        acc[2] += d * d;
        // ce = log(sum(exp(sm))) - sm[argmax(tcls)], sm = softmax(logits).
        // sm in [0,1] -> shiftless second LSE is numerically safe.
        float mx = -1e30f;
        #pragma unroll
        for (int k = 0; k < 20; k++) mx = fmaxf(mx, p[10 + k]);
        float sm[20];
        float den = 0.f;
        #pragma unroll
        for (int k = 0; k < 20; k++) { sm[k] = __expf(p[10 + k] - mx); den += sm[k]; }
        float inv = __fdividef(1.f, den);
        float den2 = 0.f;
        #pragma unroll
        for (int k = 0; k < 20; k++) { sm[k] *= inv; den2 += __expf(sm[k]); }
        float lse2 = __logf(den2);
        float bm = t[10]; int bi = 0;
        #pragma unroll
        for (int k = 1; k < 20; k++) { float v = t[10 + k]; if (v > bm) { bm = v; bi = k; } }
        acc[1] += lse2 - sm[bi];
    } else {
        acc[5] += 1.f;
        float d0 = p[4] - tconf;
        float d1 = p[9] - t[9];
        acc[3] += d0 * d0 + d1 * d1;
    }
}

__device__ __forceinline__ void block_reduce6(float* vals, float* s_red, int tid)
{
    #pragma unroll
    for (int v = 0; v < 6; v++) {
        #pragma unroll
        for (int off = 16; off > 0; off >>= 1)
            vals[v] += __shfl_down_sync(0xffffffffu, vals[v], off);
    }
    const int warp = tid >> 5;
    const int lane = tid & 31;
    if (lane == 0) {
        #pragma unroll
        for (int v = 0; v < 6; v++) s_red[warp * 6 + v] = vals[v];
    }
    __syncthreads();
    if (tid == 0) {
        #pragma unroll
        for (int v = 0; v < 6; v++)
            vals[v] = s_red[v] + s_red[6 + v] + s_red[12 + v] + s_red[18 + v];
    }
}

__global__ __launch_bounds__(THREADS)
void yolo_fused(const float* __restrict__ pred,
                const float* __restrict__ target,
                const int*   __restrict__ choice,
                float*       __restrict__ out,
                int n_cells, int n_tiles)
{
    __shared__ Stage stage[2];
    __shared__ __align__(8) unsigned long long mbar_mem[2];
    __shared__ float s_red[4 * 6];
    __shared__ bool  s_last;

    const int tid = threadIdx.x;
    float acc[6] = {0.f, 0.f, 0.f, 0.f, 0.f, 0.f};

    const int first = blockIdx.x;
    const int step  = gridDim.x;

    const uint32_t mb[2] = { smem_u32(&mbar_mem[0]), smem_u32(&mbar_mem[1]) };
    if (tid == 0) { mbar_init(mb[0], 1); mbar_init(mb[1], 1); }
    __syncthreads();

    // ---- prologue: issue TMA for the first two full tiles ----
    if (tid == 0) {
        #pragma unroll
        for (int s = 0; s < 2; s++) {
            long long t = (long long)first + (long long)s * step;
            if (t < n_tiles) {
                long long base = t * TILE;
                if (base + TILE <= n_cells) {
                    mbar_expect_tx(mb[s], STAGE_TX);
                    bulk_g2s(smem_u32(stage[s].sp), pred   + base * 30, STAGE_PT_BYTES, mb[s]);
                    bulk_g2s(smem_u32(stage[s].st), target + base * 30, STAGE_PT_BYTES, mb[s]);
                    bulk_g2s(smem_u32(stage[s].sc), choice + base,      STAGE_C_BYTES,  mb[s]);
                }
            }
        }
    }

    uint32_t phase[2] = {0u, 0u};
    int s = 0;
    for (int tile = first; tile < n_tiles; tile += step, s ^= 1) {
        const long long base_cell = (long long)tile * TILE;
        const int cells_here = (int)min((long long)TILE, (long long)n_cells - base_cell);

        if (cells_here == TILE) {
            mbar_wait(mb[s], phase[s]);
            phase[s] ^= 1u;

            const float* P = stage[s].sp + tid * 30;
            const float* T = stage[s].st + tid * 30;
            cell_compute(P, T, stage[s].sc[tid] != 0, acc);

            __syncthreads();           // all warps done reading stage s

            // reissue this stage for tile + 2*step
            const long long tn = (long long)tile + 2LL * step;
            if (tid == 0 && tn < n_tiles) {
                long long nbase = tn * TILE;
                if (nbase + TILE <= n_cells) {
                    fence_proxy_async_shared();
                    mbar_expect_tx(mb[s], STAGE_TX);
                    bulk_g2s(smem_u32(stage[s].sp), pred   + nbase * 30, STAGE_PT_BYTES, mb[s]);
                    bulk_g2s(smem_u32(stage[s].st), target + nbase * 30, STAGE_PT_BYTES, mb[s]);
                    bulk_g2s(smem_u32(stage[s].sc), choice + nbase,      STAGE_C_BYTES,  mb[s]);
                }
            }
        } else if (tid < cells_here) {
            // partial tail tile (never hit for 802816 cells): direct global reads
            const float* P = pred   + (base_cell + tid) * 30;
            const float* T = target + (base_cell + tid) * 30;
            cell_compute(P, T, choice[base_cell + tid] != 0, acc);
        }
    }

    __syncthreads();
    block_reduce6(acc, s_red, tid);

    if (tid == 0) {
        #pragma unroll
        for (int v = 0; v < 6; v++) g_part[v][blockIdx.x] = acc[v];
        __threadfence();
        unsigned int ticket = atomicAdd(&g_count, 1u);
        s_last = (ticket == gridDim.x - 1);
    }
    __syncthreads();

    if (s_last) {
        __threadfence();
        const int npart = gridDim.x;
        float a[6] = {0.f, 0.f, 0.f, 0.f, 0.f, 0.f};
        for (int i = tid; i < npart; i += THREADS) {
            #pragma unroll
            for (int v = 0; v < 6; v++) a[v] += g_part[v][i];
        }
        __syncthreads();
        block_reduce6(a, s_red, tid);
        if (tid == 0) {
            float n_obj = fmaxf(a[4], 1.f);
            float n_no  = fmaxf(a[5], 1.f);
            out[0] = 5.0f * a[0];
            out[1] = a[1] / n_obj;
            out[2] = a[2];
            out[3] = 0.5f * a[3] / n_no;
            g_count = 0;   // reset for next graph replay
        }
    }
}

extern "C" void kernel_launch(void* const* d_in, const int* in_sizes, int n_in,
                              void* d_out, int out_size)
{
    const float* pred   = (const float*)d_in[0];
    const float* target = (const float*)d_in[1];
    const int*   choice = (const int*)d_in[2];
    float* out = (float*)d_out;

    const int n_cells = in_sizes[2];
    const int n_tiles = (n_cells + TILE - 1) / TILE;

    int grid = 3 * 148;                       // 3 CTAs/SM, ~63 KB smem each
    if (grid > n_tiles) grid = n_tiles;
    if (grid > NPART_MAX) grid = NPART_MAX;

    yolo_fused<<<grid, THREADS>>>(pred, target, choice, out, n_cells, n_tiles);
}